// round 3
// baseline (speedup 1.0000x reference)
#include <cuda_runtime.h>
#include <math.h>

// Problem dims
#define BB   64      // batch
#define TT   512     // seq len
#define EE   256     // embed
#define HH   512     // hidden
#define GG   2048    // 4*HH
#define KC   64      // k-chunk (rows per staged chunk)

// SMEM tile strides (floats). k-pair-interleaved layouts:
//  wt[k2][col][2]  : 32 cols -> 64 floats/row, pad to 68 (272B, 16B-aligned)
//  ht[k2][b][2]    : 64 b    -> 128 floats/row, pad to 132 (528B, 16B-aligned)
#define WP   68
#define HP   132
#define WTF  (32 * WP)      // floats per wt buffer (2176)
#define HTF  (32 * HP)      // floats per ht buffer (4224)
#define SMEM_FLOATS (2*WTF + 2*HTF + GG)
#define SMEM_BYTES  (SMEM_FLOATS * 4)   // 59392

// ---------------- device scratch (allocation-free) ----------------
__device__ float g_X[TT * EE * BB];        // [t][e][b]  33.5 MB
__device__ float g_h1[2][2][HH * BB];      // [dir][parity][k][b]
__device__ float g_h2[2][2][HH * BB];
__device__ unsigned g_bar[2];
__device__ int g_tok32;                    // 1 if tokens are int32

// ---------------- helpers ----------------
__device__ __forceinline__ float sigf(float x) { return 1.0f / (1.0f + expf(-x)); }

__device__ __forceinline__ void ffma2(unsigned long long& d,
                                      unsigned long long a,
                                      unsigned long long b) {
    asm("fma.rn.f32x2 %0, %1, %2, %0;" : "+l"(d) : "l"(a), "l"(b));
}

__device__ __forceinline__ void grid_bar(unsigned* ctr, unsigned target) {
    __syncthreads();
    if (threadIdx.x == 0) {
        __threadfence();                 // release our h writes to GPU scope
        atomicAdd(ctr, 1u);
        while (*((volatile unsigned*)ctr) < target) { }
    }
    __syncthreads();
}

// ---------------- reset ----------------
__global__ void reset_kernel() {
    int i = blockIdx.x * blockDim.x + threadIdx.x;
    if (i < HH * BB) {
        #pragma unroll
        for (int d = 0; d < 2; d++)
            #pragma unroll
            for (int p = 0; p < 2; p++) { g_h1[d][p][i] = 0.0f; g_h2[d][p][i] = 0.0f; }
    }
    if (i == 0) { g_bar[0] = 0u; g_bar[1] = 0u; }
}

// ---------------- token dtype detect ----------------
// int64 little-endian tokens < 50000 -> every odd 32-bit word is 0.
__global__ void detect_kernel(const unsigned* tok) {
    __shared__ unsigned red[256];
    unsigned v = 0;
    for (int i = threadIdx.x; i < 16384; i += 256) v |= tok[2 * i + 1];
    red[threadIdx.x] = v;
    __syncthreads();
    for (int s = 128; s > 0; s >>= 1) {
        if (threadIdx.x < s) red[threadIdx.x] |= red[threadIdx.x + s];
        __syncthreads();
    }
    if (threadIdx.x == 0) g_tok32 = (red[0] != 0u) ? 1 : 0;
}

// ---------------- embedding gather (X[t][e][b]) ----------------
__global__ void gather_kernel(const void* tokens, const float* emb) {
    int t = blockIdx.x;        // 0..511
    int b = blockIdx.y;        // 0..63
    int e = threadIdx.x;       // 0..255
    long idx;
    if (g_tok32) idx = (long)((const int*)tokens)[b * TT + t];
    else         idx = (long)((const unsigned*)tokens)[(size_t)(b * TT + t) * 2];
    g_X[((size_t)t * EE + e) * BB + b] = emb[idx * EE + e];
}

// ---------------- staging (k-pair interleaved) ----------------
struct WStage { float4 a, b; };
struct HStage { float4 e0, e1, o0, o1; };

__device__ __forceinline__ void load_w(WStage& s, const float* __restrict__ Wg,
                                       int k0, int s2, int gcol) {
    const float* p = Wg + (size_t)(k0 + 2 * s2) * GG + gcol;
    s.a = *(const float4*)p;
    s.b = *(const float4*)(p + GG);
}
__device__ __forceinline__ void store_w(const WStage& s, float* wt, int s2, int sg) {
    float* d = wt + s2 * WP + sg * 8;
    ((float4*)d)[0] = make_float4(s.a.x, s.b.x, s.a.y, s.b.y);
    ((float4*)d)[1] = make_float4(s.a.z, s.b.z, s.a.w, s.b.w);
}
__device__ __forceinline__ void load_h(HStage& s, const float* __restrict__ src,
                                       int k0, int s2, int bbase) {
    const float* p = src + (size_t)(k0 + 2 * s2) * BB + bbase;
    s.e0 = __ldcg((const float4*)p);
    s.e1 = __ldcg((const float4*)(p + 4));
    s.o0 = __ldcg((const float4*)(p + BB));
    s.o1 = __ldcg((const float4*)(p + BB + 4));
}
__device__ __forceinline__ void store_h(const HStage& s, float* ht, int s2, int bbase) {
    float* d = ht + s2 * HP + bbase * 2;
    ((float4*)d)[0] = make_float4(s.e0.x, s.o0.x, s.e0.y, s.o0.y);
    ((float4*)d)[1] = make_float4(s.e0.z, s.o0.z, s.e0.w, s.o0.w);
    ((float4*)d)[2] = make_float4(s.e1.x, s.o1.x, s.e1.y, s.o1.y);
    ((float4*)d)[3] = make_float4(s.e1.z, s.o1.z, s.e1.w, s.o1.w);
}

// ---------------- inner compute: one 64-k chunk ----------------
__device__ __forceinline__ void compute_chunk(unsigned long long acc2[8],
                                              const float* wt, const float* ht,
                                              int b, int cg) {
    #pragma unroll 8
    for (int kp = 0; kp < KC / 2; kp++) {
        unsigned long long hv = *(const unsigned long long*)(ht + kp * HP + 2 * b);
        const ulonglong2* w = (const ulonglong2*)(wt + kp * WP + cg * 16);
        ulonglong2 w0 = w[0], w1 = w[1], w2 = w[2], w3 = w[3];
        ffma2(acc2[0], w0.x, hv); ffma2(acc2[1], w0.y, hv);
        ffma2(acc2[2], w1.x, hv); ffma2(acc2[3], w1.y, hv);
        ffma2(acc2[4], w2.x, hv); ffma2(acc2[5], w2.y, hv);
        ffma2(acc2[6], w3.x, hv); ffma2(acc2[7], w3.y, hv);
    }
}

// ---------------- pipelined GEMM: acc += src^T @ W slice ----------------
__device__ __forceinline__ void gemm_pipe(unsigned long long acc2[8],
    const float* __restrict__ src, int nk, const float* __restrict__ Wg, int ub,
    int tid, int b, int cg,
    float* wt0, float* wt1, float* ht0, float* ht1)
{
    const int s2 = tid & 31;       // k-pair row staged by this thread
    const int sg = tid >> 5;       // staging group: gate=sg>>1, half=sg&1
    const int bbase = sg * 8;
    const int gcol = (sg >> 1) * HH + ub + (sg & 1) * 4;
    const int n = nk / KC;

    WStage ws; HStage hs;
    load_w(ws, Wg, 0, s2, gcol);
    load_h(hs, src, 0, s2, bbase);
    store_w(ws, wt0, s2, sg);
    store_h(hs, ht0, s2, bbase);
    __syncthreads();
    for (int c = 0; c < n; c++) {
        float* wtc = (c & 1) ? wt1 : wt0;
        float* htc = (c & 1) ? ht1 : ht0;
        float* wtn = (c & 1) ? wt0 : wt1;
        float* htn = (c & 1) ? ht0 : ht1;
        if (c + 1 < n) {
            load_w(ws, Wg, (c + 1) * KC, s2, gcol);
            load_h(hs, src, (c + 1) * KC, s2, bbase);
        }
        compute_chunk(acc2, wtc, htc, b, cg);
        if (c + 1 < n) {
            store_w(ws, wtn, s2, sg);
            store_h(hs, htn, s2, bbase);
        }
        __syncthreads();
    }
}

// ---------------- persistent BiLSTM kernel ----------------
__global__ void __launch_bounds__(256, 1) lstm_kernel(
    const float* __restrict__ W1f, const float* __restrict__ U1f, const float* __restrict__ b1f,
    const float* __restrict__ W2f, const float* __restrict__ U2f, const float* __restrict__ b2f,
    const float* __restrict__ W1b, const float* __restrict__ U1b, const float* __restrict__ b1b,
    const float* __restrict__ W2b, const float* __restrict__ U2b, const float* __restrict__ b2b)
{
    const int dir = blockIdx.x >> 6;     // 0 = fwd, 1 = bwd
    const int cid = blockIdx.x & 63;     // CTA within direction
    const int ub  = cid * 8;             // base hidden unit
    const int tid = threadIdx.x;
    const int b   = tid & 63;
    const int cg  = tid >> 6;            // gate: 0=i 1=f 2=g 3=o

    const float *W1, *U1, *b1, *W2, *U2, *b2;
    if (dir == 0) { W1 = W1f; U1 = U1f; b1 = b1f; W2 = W2f; U2 = U2f; b2 = b2f; }
    else          { W1 = W1b; U1 = U1b; b1 = b1b; W2 = W2b; U2 = U2b; b2 = b2b; }

    extern __shared__ float smem[];
    float* wt0 = smem;
    float* wt1 = wt0 + WTF;
    float* ht0 = wt1 + WTF;
    float* ht1 = ht0 + HTF;
    float* zb  = ht1 + HTF;              // [32 local cols][64 b]

    // cell state in registers: this thread owns p=tid (u=tid>>6) and p=tid+256 (u+4)
    float c1_0 = 0.0f, c1_1 = 0.0f, c2_0 = 0.0f, c2_1 = 0.0f;
    unsigned target = 0;
    float* h1w[2] = { g_h1[dir][0], g_h1[dir][1] };
    float* h2w[2] = { g_h2[dir][0], g_h2[dir][1] };

    for (int t = 0; t < TT; t++) {
        const int ttx = dir ? (TT - 1 - t) : t;
        const int wp = t & 1, rp = wp ^ 1;

        // ================= Phase A: layer-1 gates =================
        unsigned long long acc2[8];
        #pragma unroll
        for (int j = 0; j < 8; j++) acc2[j] = 0ull;
        gemm_pipe(acc2, g_X + (size_t)ttx * EE * BB, EE, W1, ub, tid, b, cg, wt0, wt1, ht0, ht1);
        gemm_pipe(acc2, h1w[rp], HH, U1, ub, tid, b, cg, wt0, wt1, ht0, ht1);

        #pragma unroll
        for (int j = 0; j < 8; j++) {
            float lo = __int_as_float((int)(acc2[j] & 0xffffffffull));
            float hi = __int_as_float((int)(acc2[j] >> 32));
            zb[(cg * 8 + j) * BB + b] = lo + hi + b1[cg * HH + ub + j];
        }
        __syncthreads();
        {
            int u = tid >> 6, bb2 = tid & 63;
            float iv = zb[( 0 + u) * BB + bb2];
            float fv = zb[( 8 + u) * BB + bb2];
            float gv = zb[(16 + u) * BB + bb2];
            float ov = zb[(24 + u) * BB + bb2];
            float c = sigf(fv) * c1_0 + sigf(iv) * tanhf(gv);
            c1_0 = c;
            __stcg(&h1w[wp][(ub + u) * BB + bb2], sigf(ov) * tanhf(c));
            u += 4;
            iv = zb[( 0 + u) * BB + bb2];
            fv = zb[( 8 + u) * BB + bb2];
            gv = zb[(16 + u) * BB + bb2];
            ov = zb[(24 + u) * BB + bb2];
            c = sigf(fv) * c1_1 + sigf(iv) * tanhf(gv);
            c1_1 = c;
            __stcg(&h1w[wp][(ub + u) * BB + bb2], sigf(ov) * tanhf(c));
        }
        target += 64;
        grid_bar(&g_bar[dir], target);

        // ================= Phase B: layer-2 gates =================
        #pragma unroll
        for (int j = 0; j < 8; j++) acc2[j] = 0ull;
        gemm_pipe(acc2, h1w[wp], HH, W2, ub, tid, b, cg, wt0, wt1, ht0, ht1);
        gemm_pipe(acc2, h2w[rp], HH, U2, ub, tid, b, cg, wt0, wt1, ht0, ht1);

        #pragma unroll
        for (int j = 0; j < 8; j++) {
            float lo = __int_as_float((int)(acc2[j] & 0xffffffffull));
            float hi = __int_as_float((int)(acc2[j] >> 32));
            zb[(cg * 8 + j) * BB + b] = lo + hi + b2[cg * HH + ub + j];
        }
        __syncthreads();
        {
            int u = tid >> 6, bb2 = tid & 63;
            float iv = zb[( 0 + u) * BB + bb2];
            float fv = zb[( 8 + u) * BB + bb2];
            float gv = zb[(16 + u) * BB + bb2];
            float ov = zb[(24 + u) * BB + bb2];
            float c = sigf(fv) * c2_0 + sigf(iv) * tanhf(gv);
            c2_0 = c;
            __stcg(&h2w[wp][(ub + u) * BB + bb2], sigf(ov) * tanhf(c));
            u += 4;
            iv = zb[( 0 + u) * BB + bb2];
            fv = zb[( 8 + u) * BB + bb2];
            gv = zb[(16 + u) * BB + bb2];
            ov = zb[(24 + u) * BB + bb2];
            c = sigf(fv) * c2_1 + sigf(iv) * tanhf(gv);
            c2_1 = c;
            __stcg(&h2w[wp][(ub + u) * BB + bb2], sigf(ov) * tanhf(c));
        }
        target += 64;
        grid_bar(&g_bar[dir], target);
    }
}

// ---------------- final dense head ----------------
__global__ void dense_kernel(const float* __restrict__ Wd, const float* __restrict__ bd,
                             float* __restrict__ out) {
    int tid = threadIdx.x;
    if (tid >= 320) return;
    int bb2 = tid / 5, o = tid % 5;
    float s = bd[o];
    for (int j = 0; j < HH; j++) s += g_h2[0][1][j * BB + bb2] * Wd[j * 5 + o];
    for (int j = 0; j < HH; j++) s += g_h2[1][1][j * BB + bb2] * Wd[(HH + j) * 5 + o];
    out[bb2 * 5 + o] = s;
}

// ---------------- launch ----------------
extern "C" void kernel_launch(void* const* d_in, const int* in_sizes, int n_in,
                              void* d_out, int out_size) {
    const void*  tokens = d_in[0];
    const float* emb = (const float*)d_in[1];
    const float* W1f = (const float*)d_in[2];
    const float* U1f = (const float*)d_in[3];
    const float* b1f = (const float*)d_in[4];
    const float* W2f = (const float*)d_in[5];
    const float* U2f = (const float*)d_in[6];
    const float* b2f = (const float*)d_in[7];
    const float* W1b = (const float*)d_in[8];
    const float* U1b = (const float*)d_in[9];
    const float* b1b = (const float*)d_in[10];
    const float* W2b = (const float*)d_in[11];
    const float* U2b = (const float*)d_in[12];
    const float* b2b = (const float*)d_in[13];
    const float* Wd  = (const float*)d_in[14];
    const float* bd  = (const float*)d_in[15];
    float* out = (float*)d_out;

    cudaFuncSetAttribute(lstm_kernel, cudaFuncAttributeMaxDynamicSharedMemorySize, SMEM_BYTES);

    reset_kernel<<<128, 256>>>();
    detect_kernel<<<1, 256>>>((const unsigned*)tokens);
    dim3 gg(TT, BB);
    gather_kernel<<<gg, 256>>>(tokens, emb);
    lstm_kernel<<<128, 256, SMEM_BYTES>>>(W1f, U1f, b1f, W2f, U2f, b2f,
                                          W1b, U1b, b1b, W2b, U2b, b2b);
    dense_kernel<<<1, 320>>>(Wd, bd, out);
}

// round 4
// speedup vs baseline: 1.2376x; 1.2376x over previous
#include <cuda_runtime.h>
#include <math.h>

// Problem dims
#define BB   64      // batch
#define TT   512     // seq len
#define EE   256     // embed
#define HH   512     // hidden
#define GG   2048    // 4*HH
#define KC   64      // k rows per staged chunk (32 k-pairs)

// SMEM tiles, k-pair interleaved:
//   wt[kp][col][2] : 32 cols -> 64 floats/row, pad to 68
//   ht[kp][b][2]   : 64 b    -> 128 floats/row, pad to 132
#define WP   68
#define HP   132
#define WTF  (32 * WP)     // 2176 floats per buffer
#define HTF  (32 * HP)     // 4224 floats per buffer
#define ZBF  (32 * BB)     // 2048 floats
#define SMEM_BYTES ((2*WTF + 2*HTF + ZBF) * 4)   // 59392

// ---------------- device scratch (allocation-free) ----------------
__device__ float g_X[TT * EE * BB];        // [t][e][b]
__device__ float g_h1[2][2][HH * BB];      // [dir][parity][k][b]
__device__ float g_h2[2][2][HH * BB];
__device__ unsigned g_bar[2];
__device__ int g_tok32;

// ---------------- helpers ----------------
__device__ __forceinline__ float fsig(float x) { return 1.0f / (1.0f + __expf(-x)); }
__device__ __forceinline__ float ftanh(float x) {
    // tanh(x) = 2*sigmoid(2x) - 1   (abs err ~1e-6 with __expf)
    return 2.0f / (1.0f + __expf(-2.0f * x)) - 1.0f;
}

__device__ __forceinline__ void ffma2(unsigned long long& d,
                                      unsigned long long a,
                                      unsigned long long b) {
    asm("fma.rn.f32x2 %0, %1, %2, %0;" : "+l"(d) : "l"(a), "l"(b));
}

__device__ __forceinline__ void grid_bar(unsigned* ctr, unsigned target) {
    __syncthreads();
    if (threadIdx.x == 0) {
        __threadfence();
        atomicAdd(ctr, 1u);
        while (*((volatile unsigned*)ctr) < target) { }
    }
    __syncthreads();
}

// ---------------- reset ----------------
__global__ void reset_kernel() {
    int i = blockIdx.x * blockDim.x + threadIdx.x;
    if (i < HH * BB) {
        #pragma unroll
        for (int d = 0; d < 2; d++)
            #pragma unroll
            for (int p = 0; p < 2; p++) { g_h1[d][p][i] = 0.0f; g_h2[d][p][i] = 0.0f; }
    }
    if (i == 0) { g_bar[0] = 0u; g_bar[1] = 0u; }
}

// ---------------- token dtype detect ----------------
__global__ void detect_kernel(const unsigned* tok) {
    __shared__ unsigned red[256];
    unsigned v = 0;
    for (int i = threadIdx.x; i < 16384; i += 256) v |= tok[2 * i + 1];
    red[threadIdx.x] = v;
    __syncthreads();
    for (int s = 128; s > 0; s >>= 1) {
        if (threadIdx.x < s) red[threadIdx.x] |= red[threadIdx.x + s];
        __syncthreads();
    }
    if (threadIdx.x == 0) g_tok32 = (red[0] != 0u) ? 1 : 0;
}

// ---------------- embedding gather (X[t][e][b]) ----------------
__global__ void gather_kernel(const void* tokens, const float* emb) {
    int t = blockIdx.x;
    int b = blockIdx.y;
    int e = threadIdx.x;
    long idx;
    if (g_tok32) idx = (long)((const int*)tokens)[b * TT + t];
    else         idx = (long)((const unsigned*)tokens)[(size_t)(b * TT + t) * 2];
    g_X[((size_t)t * EE + e) * BB + b] = emb[idx * EE + e];
}

// ---------------- staging fragments ----------------
struct WStage { float2 a, b; };     // two k rows, two cols
struct HStage { float4 e, o; };     // two k rows, four b

__device__ __forceinline__ void load_w(WStage& s, const float* __restrict__ Wg,
                                       int k0, int s2, int gcol) {
    const float* p = Wg + (size_t)(k0 + 2 * s2) * GG + gcol;
    s.a = *(const float2*)p;
    s.b = *(const float2*)(p + GG);
}
__device__ __forceinline__ void store_w(const WStage& s, float* wt, int s2, int cp) {
    *(float4*)(wt + s2 * WP + 4 * cp) = make_float4(s.a.x, s.b.x, s.a.y, s.b.y);
}
__device__ __forceinline__ void load_h(HStage& s, const float* __restrict__ src,
                                       int k0, int s2, int bq) {
    const float* p = src + (size_t)(k0 + 2 * s2) * BB + 4 * bq;
    s.e = __ldcg((const float4*)p);
    s.o = __ldcg((const float4*)(p + BB));
}
__device__ __forceinline__ void store_h(const HStage& s, float* ht, int s2, int bq) {
    float* d = ht + s2 * HP + 8 * bq;
    ((float4*)d)[0] = make_float4(s.e.x, s.o.x, s.e.y, s.o.y);
    ((float4*)d)[1] = make_float4(s.e.z, s.o.z, s.e.w, s.o.w);
}

// ---------------- inner compute: one 64-k chunk, 4 cols/thread ----------------
__device__ __forceinline__ void compute_chunk(unsigned long long acc2[4],
                                              const float* wt, const float* ht,
                                              int b, int q) {
    #pragma unroll 16
    for (int kp = 0; kp < KC / 2; kp++) {
        unsigned long long hv = *(const unsigned long long*)(ht + kp * HP + 2 * b);
        const float* wrow = wt + kp * WP + q * 8;
        ulonglong2 w0 = *(const ulonglong2*)wrow;
        ulonglong2 w1 = *(const ulonglong2*)(wrow + 4);
        ffma2(acc2[0], w0.x, hv);
        ffma2(acc2[1], w0.y, hv);
        ffma2(acc2[2], w1.x, hv);
        ffma2(acc2[3], w1.y, hv);
    }
}

// ---------------- pipelined GEMM: acc += src^T @ W slice ----------------
__device__ __forceinline__ void gemm_pipe(unsigned long long acc2[4],
    const float* __restrict__ src, int nk, const float* __restrict__ Wg, int ub,
    int tid, int b, int q,
    float* wt0, float* wt1, float* ht0, float* ht1)
{
    const int s2 = tid >> 4;        // k-pair row 0..31
    const int cp = tid & 15;        // col-pair 0..15 / b-quad 0..15
    const int gcol = (cp >> 2) * HH + ub + (cp & 3) * 2;
    const int n = nk / KC;

    WStage ws; HStage hs;
    load_w(ws, Wg, 0, s2, gcol);
    load_h(hs, src, 0, s2, cp);
    store_w(ws, wt0, s2, cp);
    store_h(hs, ht0, s2, cp);
    __syncthreads();
    for (int c = 0; c < n; c++) {
        const float* wtc = (c & 1) ? wt1 : wt0;
        const float* htc = (c & 1) ? ht1 : ht0;
        float* wtn = (c & 1) ? wt0 : wt1;
        float* htn = (c & 1) ? ht0 : ht1;
        if (c + 1 < n) {
            load_w(ws, Wg, (c + 1) * KC, s2, gcol);
            load_h(hs, src, (c + 1) * KC, s2, cp);
        }
        compute_chunk(acc2, wtc, htc, b, q);
        if (c + 1 < n) {
            store_w(ws, wtn, s2, cp);
            store_h(hs, htn, s2, cp);
        }
        __syncthreads();
    }
}

// ---------------- persistent BiLSTM kernel ----------------
__global__ void __launch_bounds__(512, 1) lstm_kernel(
    const float* __restrict__ W1f, const float* __restrict__ U1f, const float* __restrict__ b1f,
    const float* __restrict__ W2f, const float* __restrict__ U2f, const float* __restrict__ b2f,
    const float* __restrict__ W1b, const float* __restrict__ U1b, const float* __restrict__ b1b,
    const float* __restrict__ W2b, const float* __restrict__ U2b, const float* __restrict__ b2b)
{
    const int dir = blockIdx.x >> 6;
    const int cid = blockIdx.x & 63;
    const int ub  = cid * 8;             // base hidden unit (8 units, 32 gate cols)
    const int tid = threadIdx.x;
    const int b   = tid & 63;            // batch lane
    const int q   = tid >> 6;            // col quad 0..7 (gate = q>>1, units (q&1)*4..+3)

    const float *W1, *U1, *b1, *W2, *U2, *b2;
    if (dir == 0) { W1 = W1f; U1 = U1f; b1 = b1f; W2 = W2f; U2 = U2f; b2 = b2f; }
    else          { W1 = W1b; U1 = U1b; b1 = b1b; W2 = W2b; U2 = U2b; b2 = b2b; }

    extern __shared__ float smem[];
    float* wt0 = smem;
    float* wt1 = wt0 + WTF;
    float* ht0 = wt1 + WTF;
    float* ht1 = ht0 + HTF;
    float* zb  = ht1 + HTF;              // [32 local cols][64 b]

    // bias quads for this thread's 4 cols (constant over t)
    const float4 b1v = *(const float4*)(b1 + (q >> 1) * HH + ub + (q & 1) * 4);
    const float4 b2v = *(const float4*)(b2 + (q >> 1) * HH + ub + (q & 1) * 4);

    // pointwise mapping: this thread owns (u = tid>>6, b) -> one cell elem/layer
    const int pu = tid >> 6;             // unit 0..7
    // zb row for (gate g, unit pu): ((g*2 + (pu>>2))*4 + (pu&3))
    const int zr0 = ((0 + (pu >> 2)) * 4 + (pu & 3)) * BB + b;   // gate 0 row offset
    // other gates add 8*BB per gate in this indexing:
    // row(g) = (g*2 + (pu>>2))*4 + (pu&3) = row(0) + g*8
    float c1 = 0.0f, c2 = 0.0f;
    unsigned target = 0;
    float* h1w[2] = { g_h1[dir][0], g_h1[dir][1] };
    float* h2w[2] = { g_h2[dir][0], g_h2[dir][1] };

    for (int t = 0; t < TT; t++) {
        const int ttx = dir ? (TT - 1 - t) : t;
        const int wp = t & 1, rp = wp ^ 1;

        // ================= Phase A: layer 1 =================
        unsigned long long acc2[4];
        #pragma unroll
        for (int j = 0; j < 4; j++) acc2[j] = 0ull;
        gemm_pipe(acc2, g_X + (size_t)ttx * EE * BB, EE, W1, ub, tid, b, q, wt0, wt1, ht0, ht1);
        gemm_pipe(acc2, h1w[rp], HH, U1, ub, tid, b, q, wt0, wt1, ht0, ht1);

        {
            const float* bp = (const float*)&b1v;
            #pragma unroll
            for (int j = 0; j < 4; j++) {
                float lo = __int_as_float((int)(acc2[j] & 0xffffffffull));
                float hi = __int_as_float((int)(acc2[j] >> 32));
                zb[(q * 4 + j) * BB + b] = lo + hi + bp[j];
            }
        }
        __syncthreads();
        {
            float iv = zb[zr0];
            float fv = zb[zr0 +  8 * BB];
            float gv = zb[zr0 + 16 * BB];
            float ov = zb[zr0 + 24 * BB];
            c1 = fsig(fv) * c1 + fsig(iv) * ftanh(gv);
            __stcg(&h1w[wp][(ub + pu) * BB + b], fsig(ov) * ftanh(c1));
        }
        target += 64;
        grid_bar(&g_bar[dir], target);

        // ================= Phase B: layer 2 =================
        #pragma unroll
        for (int j = 0; j < 4; j++) acc2[j] = 0ull;
        gemm_pipe(acc2, h1w[wp], HH, W2, ub, tid, b, q, wt0, wt1, ht0, ht1);
        gemm_pipe(acc2, h2w[rp], HH, U2, ub, tid, b, q, wt0, wt1, ht0, ht1);

        {
            const float* bp = (const float*)&b2v;
            #pragma unroll
            for (int j = 0; j < 4; j++) {
                float lo = __int_as_float((int)(acc2[j] & 0xffffffffull));
                float hi = __int_as_float((int)(acc2[j] >> 32));
                zb[(q * 4 + j) * BB + b] = lo + hi + bp[j];
            }
        }
        __syncthreads();
        {
            float iv = zb[zr0];
            float fv = zb[zr0 +  8 * BB];
            float gv = zb[zr0 + 16 * BB];
            float ov = zb[zr0 + 24 * BB];
            c2 = fsig(fv) * c2 + fsig(iv) * ftanh(gv);
            __stcg(&h2w[wp][(ub + pu) * BB + b], fsig(ov) * ftanh(c2));
        }
        target += 64;
        grid_bar(&g_bar[dir], target);
    }
}

// ---------------- final dense head ----------------
__global__ void dense_kernel(const float* __restrict__ Wd, const float* __restrict__ bd,
                             float* __restrict__ out) {
    int tid = threadIdx.x;
    if (tid >= 320) return;
    int bb2 = tid / 5, o = tid % 5;
    float s = bd[o];
    for (int j = 0; j < HH; j++) s += g_h2[0][1][j * BB + bb2] * Wd[j * 5 + o];
    for (int j = 0; j < HH; j++) s += g_h2[1][1][j * BB + bb2] * Wd[(HH + j) * 5 + o];
    out[bb2 * 5 + o] = s;
}

// ---------------- launch ----------------
extern "C" void kernel_launch(void* const* d_in, const int* in_sizes, int n_in,
                              void* d_out, int out_size) {
    const void*  tokens = d_in[0];
    const float* emb = (const float*)d_in[1];
    const float* W1f = (const float*)d_in[2];
    const float* U1f = (const float*)d_in[3];
    const float* b1f = (const float*)d_in[4];
    const float* W2f = (const float*)d_in[5];
    const float* U2f = (const float*)d_in[6];
    const float* b2f = (const float*)d_in[7];
    const float* W1b = (const float*)d_in[8];
    const float* U1b = (const float*)d_in[9];
    const float* b1b = (const float*)d_in[10];
    const float* W2b = (const float*)d_in[11];
    const float* U2b = (const float*)d_in[12];
    const float* b2b = (const float*)d_in[13];
    const float* Wd  = (const float*)d_in[14];
    const float* bd  = (const float*)d_in[15];
    float* out = (float*)d_out;

    cudaFuncSetAttribute(lstm_kernel, cudaFuncAttributeMaxDynamicSharedMemorySize, SMEM_BYTES);

    reset_kernel<<<128, 256>>>();
    detect_kernel<<<1, 256>>>((const unsigned*)tokens);
    dim3 gg(TT, BB);
    gather_kernel<<<gg, 256>>>(tokens, emb);
    lstm_kernel<<<128, 512, SMEM_BYTES>>>(W1f, U1f, b1f, W2f, U2f, b2f,
                                          W1b, U1b, b1b, W2b, U2b, b2b);
    dense_kernel<<<1, 320>>>(Wd, bd, out);
}